// round 2
// baseline (speedup 1.0000x reference)
#include <cuda_runtime.h>
#include <math.h>

// ---------------- problem constants ----------------
#define NN 100000
#define EE 3200000
#define HH 64
#define DD 256

// ---------------- scratch (device globals; no runtime alloc) ----------------
__device__ __align__(128) float g_xu[NN * HH];     // x@Wu -> BN'd
__device__ __align__(128) float g_su[NN * HH];     // y@Wp -> BN'd
__device__ __align__(128) float g_ew[EE];          // logit
__device__ __align__(128) float g_m[NN];           // segment max (float bits)
__device__ __align__(128) float g_denom[NN];       // segment sum of ex
__device__ __align__(128) float g_agg[NN * HH];    // UNNORMALIZED weighted neighbor sum
__device__ __align__(128) float g_h1[NN * HH];     // CRF result
__device__ __align__(128) float g_t2[NN * DD];     // h1@Wm raw -> h2
__device__ __align__(128) float g_t3[NN * DD];     // concat@Wf raw
__device__ __align__(16) float g_C[HH * HH];
__device__ __align__(16) float g_A12[2 * HH * HH]; // [Minv ; C@Minv] stacked (128 x 64)
__device__ float g_ssum[DD];
__device__ float g_ssq[DD];
__device__ int g_idx64;

// ---------------- index dtype handling ----------------
__global__ void k_detect(const unsigned int* p) {
    if (threadIdx.x == 0 && blockIdx.x == 0) {
        int is64 = 1;
        for (int k = 1; k < 64; k += 2) {
            if (p[k] != 0u) { is64 = 0; break; }
        }
        g_idx64 = is64;
    }
}

__device__ __forceinline__ int load_idx(const void* p, long k) {
    if (g_idx64) return (int)(((const long long*)p)[k]);
    return ((const int*)p)[k];
}

// ---------------- init ----------------
__global__ void k_init(int n) {
    long total = (long)n * HH + 2L * n;
    long idx = (long)blockIdx.x * blockDim.x + threadIdx.x;
    if (idx >= total) return;
    long a = (long)n * HH;
    if (idx < a) {
        g_agg[idx] = 0.0f;
    } else if (idx < a + n) {
        g_denom[idx - a] = 0.0f;
    } else {
        ((unsigned int*)g_m)[idx - a - n] = 0xFF800000u;  // -inf
    }
}

__global__ void k_zstat() {
    int t = threadIdx.x;
    if (t < DD) { g_ssum[t] = 0.0f; g_ssq[t] = 0.0f; }
}

// ---------------- CRF matrix prep: C = c^T c, A12 = [inv(I+C) ; C inv(I+C)] ----------------
__global__ void k_prep_crf(const float* __restrict__ c) {
    __shared__ __align__(16) float Maug[HH][2 * HH + 1];  // [64][129]
    int tid = threadIdx.x;
    // C = c^T c ; M = I + C ; right half = I
    for (int idx = tid; idx < HH * HH; idx += 256) {
        int a = idx >> 6, b = idx & 63;
        float s = 0.0f;
        for (int k = 0; k < HH; k++) s += c[k * HH + a] * c[k * HH + b];
        g_C[idx] = s;
        Maug[a][b] = s + (a == b ? 1.0f : 0.0f);
        Maug[a][HH + b] = (a == b ? 1.0f : 0.0f);
    }
    __syncthreads();
    // Gauss-Jordan (SPD, diagonally dominant enough; no pivoting)
    for (int p = 0; p < HH; p++) {
        float pinv = 1.0f / Maug[p][p];
        __syncthreads();
        if (tid < 2 * HH) Maug[p][tid] *= pinv;
        __syncthreads();
        int r = tid & 63, cs = tid >> 6;  // 4 col-segments of 32
        float f = (r != p) ? Maug[r][p] : 0.0f;
        __syncthreads();
        if (r != p) {
            #pragma unroll 8
            for (int q = 0; q < 32; q++) {
                int col = cs * 32 + q;
                Maug[r][col] -= f * Maug[p][col];
            }
        }
        __syncthreads();
    }
    // A12 top: Minv
    for (int idx = tid; idx < HH * HH; idx += 256) {
        int a = idx >> 6, b = idx & 63;
        g_A12[idx] = Maug[a][HH + b];
    }
    __syncthreads();
    // A12 bottom: C @ Minv
    for (int idx = tid; idx < HH * HH; idx += 256) {
        int a = idx >> 6, b = idx & 63;
        float s = 0.0f;
        for (int k = 0; k < HH; k++) s += g_C[a * HH + k] * Maug[k][HH + b];
        g_A12[HH * HH + idx] = s;
    }
}

// ---------------- tiled SGEMM: out[n,CO] = A[n,K] @ W[K,CO] ----------------
// CONCAT: logical A = cat(A, A2s) along features (each K/2 wide)
// SCALE2: rows of A2s are scaled by 1/(g_denom[row]+1e-16)
template <int K, int CO, int BN, int TN, bool CONCAT, bool SCALE2>
__global__ __launch_bounds__(256) void k_gemm(
    const float* __restrict__ A, const float* __restrict__ A2s,
    const float* __restrict__ W, float* __restrict__ out, int n)
{
    constexpr int BM = 128, BK = 16, TM = 8;
    __shared__ __align__(16) float As[BK][BM + 4];
    __shared__ __align__(16) float Bs[BK][BN];
    int tid = threadIdx.x;
    int tx = tid & 15, ty = tid >> 4;
    int row0 = blockIdx.x * BM;
    int col0 = blockIdx.y * BN;
    float acc[TM][TN];
    #pragma unroll
    for (int r = 0; r < TM; r++)
        #pragma unroll
        for (int cc = 0; cc < TN; cc++) acc[r][cc] = 0.0f;

    for (int k0 = 0; k0 < K; k0 += BK) {
        // A tile: 128x16, transposed into As[kk][row]
        #pragma unroll
        for (int p = 0; p < 2; p++) {
            int idx = tid + p * 256;
            int ar = idx >> 2;
            int af = idx & 3;
            int grow = row0 + ar;
            int gk = k0 + af * 4;
            const float* src = A;
            int stride = K;
            bool second = false;
            if (CONCAT) {
                stride = K / 2;
                if (gk >= K / 2) { src = A2s; gk -= K / 2; second = true; }
            }
            float4 v = make_float4(0.f, 0.f, 0.f, 0.f);
            if (grow < n) {
                v = *(const float4*)(src + (long)grow * stride + gk);
                if (SCALE2 && second) {
                    float rs = 1.0f / (g_denom[grow] + 1e-16f);
                    v.x *= rs; v.y *= rs; v.z *= rs; v.w *= rs;
                }
            }
            As[af * 4 + 0][ar] = v.x;
            As[af * 4 + 1][ar] = v.y;
            As[af * 4 + 2][ar] = v.z;
            As[af * 4 + 3][ar] = v.w;
        }
        // B tile: 16xBN
        constexpr int BF4 = BK * BN / 4;
        #pragma unroll
        for (int p = 0; p < BF4 / 256; p++) {
            int idx = tid + p * 256;
            int br = idx / (BN / 4);
            int bf = idx % (BN / 4);
            float4 v = *(const float4*)(W + (long)(k0 + br) * CO + col0 + bf * 4);
            *(float4*)&Bs[br][bf * 4] = v;
        }
        __syncthreads();
        #pragma unroll
        for (int kk = 0; kk < BK; kk++) {
            float a[TM], b[TN];
            *(float4*)&a[0] = *(const float4*)&As[kk][ty * TM];
            *(float4*)&a[4] = *(const float4*)&As[kk][ty * TM + 4];
            *(float4*)&b[0] = *(const float4*)&Bs[kk][tx * TN];
            if (TN == 8) *(float4*)&b[4] = *(const float4*)&Bs[kk][tx * TN + 4];
            #pragma unroll
            for (int r = 0; r < TM; r++)
                #pragma unroll
                for (int cc = 0; cc < TN; cc++)
                    acc[r][cc] += a[r] * b[cc];
        }
        __syncthreads();
    }
    // epilogue
    #pragma unroll
    for (int r = 0; r < TM; r++) {
        int grow = row0 + ty * TM + r;
        if (grow >= n) continue;
        #pragma unroll
        for (int c4 = 0; c4 < TN / 4; c4++) {
            float4 v = make_float4(acc[r][c4 * 4 + 0], acc[r][c4 * 4 + 1],
                                   acc[r][c4 * 4 + 2], acc[r][c4 * 4 + 3]);
            *(float4*)(out + (long)grow * CO + col0 + tx * TN + c4 * 4) = v;
        }
    }
}

// ---------------- BN column stats ----------------
template <int C>
__global__ void k_stats(const float* __restrict__ in, int n) {
    constexpr int RL = 256 / C;
    int col = threadIdx.x % C;
    int rl = threadIdx.x / C;
    int r0 = blockIdx.x * 256;
    int rend = r0 + 256; if (rend > n) rend = n;
    float s = 0.0f, ss = 0.0f;
    for (int r = r0 + rl; r < rend; r += RL) {
        float v = in[(long)r * C + col];
        s += v; ss += v * v;
    }
    atomicAdd(&g_ssum[col], s);
    atomicAdd(&g_ssq[col], ss);
}

// ---------------- BN normalize (+optional leaky relu) ----------------
template <int C, bool LEAKY>
__global__ void k_norm(const float* __restrict__ in, float* __restrict__ out,
                       const float* __restrict__ gamma, const float* __restrict__ beta,
                       int n)
{
    __shared__ float sc[C], sh[C];
    if (threadIdx.x < C) {
        float fn = (float)n;
        float mu = g_ssum[threadIdx.x] / fn;
        float var = g_ssq[threadIdx.x] / fn - mu * mu;
        float scale = gamma[threadIdx.x] * rsqrtf(var + 1e-5f);
        sc[threadIdx.x] = scale;
        sh[threadIdx.x] = beta[threadIdx.x] - mu * scale;
    }
    __syncthreads();
    long total4 = (long)n * C / 4;
    long idx = (long)blockIdx.x * blockDim.x + threadIdx.x;
    if (idx >= total4) return;
    float4 v = ((const float4*)in)[idx];
    int cb = (int)((idx * 4) % C);
    float r0 = v.x * sc[cb + 0] + sh[cb + 0];
    float r1 = v.y * sc[cb + 1] + sh[cb + 1];
    float r2 = v.z * sc[cb + 2] + sh[cb + 2];
    float r3 = v.w * sc[cb + 3] + sh[cb + 3];
    if (LEAKY) {
        r0 = r0 > 0.f ? r0 : 0.01f * r0;
        r1 = r1 > 0.f ? r1 : 0.01f * r1;
        r2 = r2 > 0.f ? r2 : 0.01f * r2;
        r3 = r3 > 0.f ? r3 : 0.01f * r3;
    }
    ((float4*)out)[idx] = make_float4(r0, r1, r2, r3);
}

// ---------------- edge pass 1: logits + segment max ----------------
__global__ void k_edge_logit(const void* __restrict__ eidx, long E) {
    long g = (long)blockIdx.x * blockDim.x + threadIdx.x;
    long e = g >> 3;
    int l8 = (int)(g & 7);
    if (e >= E) return;
    int i = load_idx(eidx, e);
    int j = load_idx(eidx, E + e);
    const float4* a = (const float4*)(g_su + (long)i * HH) + l8 * 2;
    const float4* b = (const float4*)(g_su + (long)j * HH) + l8 * 2;
    float4 a0 = a[0], a1 = a[1], b0 = b[0], b1 = b[1];
    float d0 = a0.x - b0.x, d1 = a0.y - b0.y, d2 = a0.z - b0.z, d3 = a0.w - b0.w;
    float d4 = a1.x - b1.x, d5 = a1.y - b1.y, d6 = a1.z - b1.z, d7 = a1.w - b1.w;
    float acc = d0 * d0 + d1 * d1 + d2 * d2 + d3 * d3
              + d4 * d4 + d5 * d5 + d6 * d6 + d7 * d7;
    unsigned int gmask = 0xFFu << (threadIdx.x & 24);
    acc += __shfl_xor_sync(gmask, acc, 1);
    acc += __shfl_xor_sync(gmask, acc, 2);
    acc += __shfl_xor_sync(gmask, acc, 4);
    if (l8 == 0) {
        float lg = -acc;
        g_ew[e] = lg;
        atomicMin((unsigned int*)&g_m[i], __float_as_uint(lg));
    }
}

// ---------------- edge pass 2 (fused): ex = exp(logit - m[i]); denom += ex; agg[i] += ex*xu[j]
__device__ __forceinline__ void red_add_v4(float* p, float4 v) {
    asm volatile("red.global.add.v4.f32 [%0], {%1,%2,%3,%4};"
                 :: "l"(p), "f"(v.x), "f"(v.y), "f"(v.z), "f"(v.w) : "memory");
}

__global__ void k_edge_expagg(const void* __restrict__ eidx, long E) {
    long g = (long)blockIdx.x * blockDim.x + threadIdx.x;
    long e = g >> 3;
    int l8 = (int)(g & 7);
    if (e >= E) return;
    int i = load_idx(eidx, e);
    int j = load_idx(eidx, E + e);
    float ex = expf(g_ew[e] - g_m[i]);      // broadcast loads, each lane computes
    if (l8 == 0) atomicAdd(&g_denom[i], ex);
    const float4* src = (const float4*)(g_xu + (long)j * HH) + l8 * 2;
    float* dst = g_agg + (long)i * HH + l8 * 8;
    float4 v0 = src[0], v1 = src[1];
    v0.x *= ex; v0.y *= ex; v0.z *= ex; v0.w *= ex;
    v1.x *= ex; v1.y *= ex; v1.z *= ex; v1.w *= ex;
    red_add_v4(dst, v0);
    red_add_v4(dst + 4, v1);
}

// ---------------- launch ----------------
extern "C" void kernel_launch(void* const* d_in, const int* in_sizes, int n_in,
                              void* d_out, int out_size) {
    const float* x   = (const float*)d_in[0];
    const float* y   = (const float*)d_in[1];
    const void*  eix = d_in[3];
    const float* Wu  = (const float*)d_in[4];
    const float* gu  = (const float*)d_in[5];
    const float* bu  = (const float*)d_in[6];
    const float* Wp  = (const float*)d_in[7];
    const float* gp  = (const float*)d_in[8];
    const float* bp  = (const float*)d_in[9];
    const float* cM  = (const float*)d_in[10];
    const float* Wm  = (const float*)d_in[11];
    const float* gm  = (const float*)d_in[12];
    const float* bm  = (const float*)d_in[13];
    const float* Wf  = (const float*)d_in[14];
    const float* gf  = (const float*)d_in[15];
    const float* bf  = (const float*)d_in[16];
    float* out = (float*)d_out;

    int n = in_sizes[0] / DD;
    long E = (long)in_sizes[3] / 2;

    float *xu, *su, *agg, *h1, *t2, *t3, *A12;
    cudaGetSymbolAddress((void**)&xu, g_xu);
    cudaGetSymbolAddress((void**)&su, g_su);
    cudaGetSymbolAddress((void**)&agg, g_agg);
    cudaGetSymbolAddress((void**)&h1, g_h1);
    cudaGetSymbolAddress((void**)&t2, g_t2);
    cudaGetSymbolAddress((void**)&t3, g_t3);
    cudaGetSymbolAddress((void**)&A12, g_A12);

    int rb = (n + 127) / 128;
    int sb = (n + 255) / 256;
    long init_total = (long)n * HH + 2L * n;
    int ib = (int)((init_total + 255) / 256);
    int eb8 = (int)((E * 8 + 255) / 256);
    int nb64 = (int)(((long)n * HH / 4 + 255) / 256);
    int nb256 = (int)(((long)n * DD / 4 + 255) / 256);

    k_detect<<<1, 32>>>((const unsigned int*)eix);
    k_init<<<ib, 256>>>(n);
    k_prep_crf<<<1, 256>>>(cM);

    // xu = BN(x @ Wu)
    k_gemm<256, 64, 64, 4, false, false><<<dim3(rb, 1), 256>>>(x, nullptr, Wu, xu, n);
    k_zstat<<<1, 256>>>();
    k_stats<64><<<sb, 256>>>(xu, n);
    k_norm<64, false><<<nb64, 256>>>(xu, xu, gu, bu, n);

    // su = BN(y @ Wp)
    k_gemm<256, 64, 64, 4, false, false><<<dim3(rb, 1), 256>>>(y, nullptr, Wp, su, n);
    k_zstat<<<1, 256>>>();
    k_stats<64><<<sb, 256>>>(su, n);
    k_norm<64, false><<<nb64, 256>>>(su, su, gp, bp, n);

    // edge softmax + aggregation (agg left unnormalized; scaled inside CRF gemm)
    k_edge_logit<<<eb8, 256>>>(eix, E);
    k_edge_expagg<<<eb8, 256>>>(eix, E);

    // h1 = cat(xu, agg/denom) @ [Minv ; C Minv]
    k_gemm<128, 64, 64, 4, true, true><<<dim3(rb, 1), 256>>>(xu, agg, A12, h1, n);

    // h2 = leaky(BN(h1 @ Wm))
    k_gemm<64, 256, 128, 8, false, false><<<dim3(rb, 2), 256>>>(h1, nullptr, Wm, t2, n);
    k_zstat<<<1, 256>>>();
    k_stats<256><<<sb, 256>>>(t2, n);
    k_norm<256, true><<<nb256, 256>>>(t2, t2, gm, bm, n);

    // out = leaky(BN(cat([h2, y]) @ Wf))
    k_gemm<512, 256, 128, 8, true, false><<<dim3(rb, 2), 256>>>(t2, y, Wf, t3, n);
    k_zstat<<<1, 256>>>();
    k_stats<256><<<sb, 256>>>(t3, n);
    k_norm<256, true><<<nb256, 256>>>(t3, out, gf, bf, n);
}